// round 5
// baseline (speedup 1.0000x reference)
#include <cuda_runtime.h>
#include <math.h>
#include <stdint.h>

// ---------------- problem constants ----------------
#define S_TOK   4096
#define CDIM    1024
#define EXP     64
#define TOPK    8
#define NGRP    8
#define EPG     8
#define TGRP    4
#define HDIM    512
#define HSHARED 2048
#define NROWS   (S_TOK * TOPK)   // 32768
#define MAX_TILES 320

// ---------------- scratch (static device globals) ----------------
struct TileDesc { int e; int row_start; int rows; };

__device__ int      g_counts[EXP];
__device__ int      g_offsets[EXP + 1];
__device__ int      g_cursor[EXP];
__device__ TileDesc g_tiles[MAX_TILES];
__device__ int      g_ntiles;
__device__ int      g_rowmap[NROWS];
__device__ int      g_topk_idx[NROWS];
__device__ float    g_topk_w[NROWS];

__device__ float    g_sorted_x[(size_t)NROWS * CDIM];   // tf32-rounded
__device__ float    g_gu_out[(size_t)NROWS * 1024];
__device__ float    g_hbuf[(size_t)NROWS * HDIM];       // tf32-rounded
__device__ float    g_rows_out[(size_t)NROWS * CDIM];
__device__ float    g_sh_gu[(size_t)S_TOK * 4096];
__device__ float    g_sh_h[(size_t)S_TOK * HSHARED];    // tf32-rounded
__device__ float    g_shared_out[(size_t)S_TOK * CDIM];
__device__ float    g_x_r[(size_t)S_TOK * CDIM];        // tf32-rounded x

// tf32-rounded weight copies (native [K][N] layouts preserved)
__device__ float    g_w_gate[(size_t)EXP * CDIM * HDIM];
__device__ float    g_w_up[(size_t)EXP * CDIM * HDIM];
__device__ float    g_w_down[(size_t)EXP * HDIM * CDIM];
__device__ float    g_w_shg[(size_t)CDIM * HSHARED];
__device__ float    g_w_shu[(size_t)CDIM * HSHARED];
__device__ float    g_w_shd[(size_t)HSHARED * CDIM];

// ---------------- tf32 helpers ----------------
__device__ __forceinline__ uint32_t f2tf32(float f) {
    uint32_t u;
    asm("cvt.rna.tf32.f32 %0, %1;" : "=r"(u) : "f"(f));
    return u;
}
__device__ __forceinline__ float tf32r(float f) { return __uint_as_float(f2tf32(f)); }

__device__ __forceinline__ void mma_tf32(float* c, const uint32_t* a, const uint32_t* b) {
    asm volatile(
        "mma.sync.aligned.m16n8k8.row.col.f32.tf32.tf32.f32 "
        "{%0,%1,%2,%3}, {%4,%5,%6,%7}, {%8,%9}, {%0,%1,%2,%3};"
        : "+f"(c[0]), "+f"(c[1]), "+f"(c[2]), "+f"(c[3])
        : "r"(a[0]), "r"(a[1]), "r"(a[2]), "r"(a[3]), "r"(b[0]), "r"(b[1]));
}
__device__ __forceinline__ void cp_async16(uint32_t dst, const void* src, int srcbytes) {
    asm volatile("cp.async.cg.shared.global [%0], [%1], 16, %2;"
                 :: "r"(dst), "l"(src), "r"(srcbytes));
}

// ---------------- prep: tf32-round copy ----------------
__global__ void round_copy(const float4* __restrict__ src, float4* __restrict__ dst,
                           long long n4) {
    long long i = (long long)blockIdx.x * blockDim.x + threadIdx.x;
    if (i >= n4) return;
    float4 v = src[i];
    v.x = tf32r(v.x); v.y = tf32r(v.y); v.z = tf32r(v.z); v.w = tf32r(v.w);
    dst[i] = v;
}

// ---------------- routing kernels (verified correct) ----------------
__global__ void zero_counts_kernel() {
    if (threadIdx.x < EXP) g_counts[threadIdx.x] = 0;
}

__global__ void router_kernel(const float* __restrict__ x,
                              const float* __restrict__ rw,
                              const float* __restrict__ ebias) {
    int t = blockIdx.x;
    __shared__ float xs[CDIM];
    __shared__ float sc[EXP];

    const float* xrow = x + (size_t)t * CDIM;
    for (int c = threadIdx.x * 4; c < CDIM; c += blockDim.x * 4)
        *(float4*)&xs[c] = *(const float4*)&xrow[c];
    __syncthreads();

    int wid = threadIdx.x >> 5, lane = threadIdx.x & 31;
    for (int i = 0; i < 8; i++) {
        int e = wid * 8 + i;
        const float* w = rw + (size_t)e * CDIM;
        float s = 0.f;
        for (int c = lane; c < CDIM; c += 32) s += xs[c] * w[c];
        #pragma unroll
        for (int o = 16; o > 0; o >>= 1) s += __shfl_xor_sync(0xffffffffu, s, o);
        if (lane == 0) sc[e] = 1.f / (1.f + expf(-s));
    }
    __syncthreads();

    if (threadIdx.x == 0) {
        float sb[EXP];
        for (int e = 0; e < EXP; e++) sb[e] = sc[e] + ebias[e];
        float grp[NGRP];
        for (int g = 0; g < NGRP; g++) {
            float m1 = -1e30f, m2 = -1e30f;
            for (int j = 0; j < EPG; j++) {
                float v = sb[g * EPG + j];
                if (v > m1) { m2 = m1; m1 = v; }
                else if (v > m2) m2 = v;
            }
            grp[g] = m1 + m2;
        }
        bool gsel[NGRP] = {};
        for (int it = 0; it < TGRP; it++) {
            float best = -1e30f; int bi = 0;
            for (int g = 0; g < NGRP; g++)
                if (!gsel[g] && grp[g] > best) { best = grp[g]; bi = g; }
            gsel[bi] = true;
        }
        bool eused[EXP] = {};
        int idx[TOPK]; float wv[TOPK]; float wsum = 0.f;
        for (int it = 0; it < TOPK; it++) {
            float best = -1e30f; int bi = 0;
            for (int e = 0; e < EXP; e++)
                if (gsel[e / EPG] && !eused[e] && sb[e] > best) { best = sb[e]; bi = e; }
            eused[bi] = true; idx[it] = bi;
            wv[it] = sc[bi]; wsum += sc[bi];
        }
        float inv = 1.f / (wsum + 1e-20f);
        for (int it = 0; it < TOPK; it++) {
            g_topk_idx[t * TOPK + it] = idx[it];
            g_topk_w[t * TOPK + it]   = wv[it] * inv;
            atomicAdd(&g_counts[idx[it]], 1);
        }
    }
}

__global__ void setup_kernel() {
    int off = 0, nt = 0;
    for (int e = 0; e < EXP; e++) {
        g_offsets[e] = off;
        g_cursor[e]  = off;
        int c = g_counts[e];
        for (int r = 0; r < c; r += 128) {
            g_tiles[nt].e = e;
            g_tiles[nt].row_start = off + r;
            g_tiles[nt].rows = min(128, c - r);
            nt++;
        }
        off += c;
    }
    g_offsets[EXP] = off;
    g_ntiles = nt;
}

__global__ void assign_kernel() {
    int d = blockIdx.x * blockDim.x + threadIdx.x;
    if (d >= NROWS) return;
    int e = g_topk_idx[d];
    int pos = atomicAdd(&g_cursor[e], 1);
    g_rowmap[pos] = d;
}

// gather + tf32-round into sorted order
__global__ void gather_kernel(const float* __restrict__ x) {
    int row = blockIdx.x;
    int d = g_rowmap[row];
    int t = d / TOPK;
    const float4* src = (const float4*)(x + (size_t)t * CDIM);
    float4* dst = (float4*)(g_sorted_x + (size_t)row * CDIM);
    for (int i = threadIdx.x; i < CDIM / 4; i += blockDim.x) {
        float4 v = src[i];
        v.x = tf32r(v.x); v.y = tf32r(v.y); v.z = tf32r(v.z); v.w = tf32r(v.w);
        dst[i] = v;
    }
}

// ================= tf32 tensor-core GEMM (cp.async 4-stage, 1 sync/iter) =================
// C[M,N] = A[M,Kd] @ B[Kd,N]; B row-major [k][n]. BM=128, BN=256, BK=32.
// 8 warps (2x4), warp tile 64x64. Dual-B fusion via nstart vs Nb.
#define GEMM_THREADS 256
#define STAGES 4
#define AS_STRIDE 36
#define BS_STRIDE 264
#define A_SZ (128 * AS_STRIDE)              // floats per A stage
#define B_SZ (32 * BS_STRIDE)               // floats per B stage
#define GEMM_SMEM_BYTES (STAGES * (A_SZ + B_SZ) * 4)   // 208,896 B

template <bool GROUPED, bool SCATTER>
__global__ void __launch_bounds__(GEMM_THREADS, 1) mma_gemm(
    const float* __restrict__ A, const float* __restrict__ B0,
    const float* __restrict__ B1, float* __restrict__ Cout,
    int Kd, int Nb, int N, long long strideB,
    const int* __restrict__ rowmap, const float* __restrict__ rowscale) {
    extern __shared__ float smem[];

    int row_start, rows, e;
    if (GROUPED) {
        if ((int)blockIdx.y >= g_ntiles) return;
        TileDesc td = g_tiles[blockIdx.y];
        e = td.e; row_start = td.row_start; rows = td.rows;
    } else {
        e = 0; row_start = blockIdx.y * 128; rows = 128;
    }
    int nstart = blockIdx.x * 256;
    const float* Bm = (nstart < Nb) ? B0 : B1;
    int ncol0 = (nstart < Nb) ? nstart : nstart - Nb;
    const float* Bptr = Bm + (long long)e * strideB + ncol0;
    const float* Aptr = A + (long long)row_start * Kd;

    int tid = threadIdx.x;
    int lane = tid & 31, wid = tid >> 5;
    int g = lane >> 2, tig = lane & 3;
    int wmb = (wid >> 2) * 64;
    int wnb = (wid & 3) * 64;

    uint32_t sb = (uint32_t)__cvta_generic_to_shared(smem);

    float acc[4][8][4];
    #pragma unroll
    for (int mi = 0; mi < 4; mi++)
        #pragma unroll
        for (int ni = 0; ni < 8; ni++)
            #pragma unroll
            for (int q = 0; q < 4; q++) acc[mi][ni][q] = 0.f;

    const int T = Kd >> 5;

    // issue one K-tile into `stage`
    auto issue = [&](int stage, int it) {
        int kk = it * 32;
        uint32_t abase = sb + (uint32_t)(stage * A_SZ) * 4u;
        uint32_t bbase = sb + (uint32_t)(STAGES * A_SZ + stage * B_SZ) * 4u;
        // A tile: 128 rows x 8 float4  (1024 chunks, 4/thread)
        #pragma unroll
        for (int i = 0; i < 4; i++) {
            int c = tid + i * 256;
            int r = c >> 3, j = c & 7;
            const float* src = Aptr + (long long)r * Kd + kk + j * 4;
            int vb = 16;
            if (GROUPED && r >= rows) { vb = 0; src = Aptr; }
            cp_async16(abase + (uint32_t)(r * AS_STRIDE + j * 4) * 4u, src, vb);
        }
        // B tile: 32 rows x 64 float4  (2048 chunks, 8/thread)
        #pragma unroll
        for (int i = 0; i < 8; i++) {
            int c = tid + i * 256;
            int r = c >> 6, j = c & 63;
            cp_async16(bbase + (uint32_t)(r * BS_STRIDE + j * 4) * 4u,
                       Bptr + (long long)(kk + r) * Nb + j * 4, 16);
        }
        asm volatile("cp.async.commit_group;" ::: "memory");
    };

    issue(0, 0);
    issue(1, 1);
    issue(2, 2);

    for (int it = 0; it < T; it++) {
        int stage = it & 3;
        // ensure group `it` is complete (pending groups: it..it+2 before this iter's issue)
        asm volatile("cp.async.wait_group 2;" ::: "memory");
        __syncthreads();
        // issue it+3 into a stage no warp is reading (its last readers finished iter it-1,
        // which the barrier above orders before this point)
        if (it + 3 < T) issue((it + 3) & 3, it + 3);

        const float* Ab = smem + stage * A_SZ;
        const float* Bb = smem + STAGES * A_SZ + stage * B_SZ;
        #pragma unroll
        for (int s = 0; s < 4; s++) {
            uint32_t afr[4][4], bfr[8][2];
            int k0 = s * 8 + tig;
            #pragma unroll
            for (int mi = 0; mi < 4; mi++) {
                int r0 = wmb + mi * 16 + g;
                afr[mi][0] = __float_as_uint(Ab[r0 * AS_STRIDE + k0]);
                afr[mi][1] = __float_as_uint(Ab[(r0 + 8) * AS_STRIDE + k0]);
                afr[mi][2] = __float_as_uint(Ab[r0 * AS_STRIDE + k0 + 4]);
                afr[mi][3] = __float_as_uint(Ab[(r0 + 8) * AS_STRIDE + k0 + 4]);
            }
            #pragma unroll
            for (int ni = 0; ni < 8; ni++) {
                int c0 = wnb + ni * 8 + g;
                bfr[ni][0] = __float_as_uint(Bb[k0 * BS_STRIDE + c0]);
                bfr[ni][1] = __float_as_uint(Bb[(k0 + 4) * BS_STRIDE + c0]);
            }
            #pragma unroll
            for (int mi = 0; mi < 4; mi++)
                #pragma unroll
                for (int ni = 0; ni < 8; ni++)
                    mma_tf32(acc[mi][ni], afr[mi], bfr[ni]);
        }
    }

    // ---- epilogue ----
    #pragma unroll
    for (int mi = 0; mi < 4; mi++) {
        #pragma unroll
        for (int h = 0; h < 2; h++) {
            int rl = wmb + mi * 16 + g + 8 * h;
            if (GROUPED && rl >= rows) continue;
            float scale = 1.f;
            float* dst;
            if (SCATTER) {
                int d = rowmap[row_start + rl];
                scale = rowscale[d];
                dst = Cout + (size_t)d * N;
            } else {
                dst = Cout + (size_t)(row_start + rl) * N;
            }
            #pragma unroll
            for (int ni = 0; ni < 8; ni++) {
                int col = nstart + wnb + ni * 8 + 2 * tig;
                float2 v;
                v.x = acc[mi][ni][2 * h + 0] * scale;
                v.y = acc[mi][ni][2 * h + 1] * scale;
                *(float2*)(dst + col) = v;
            }
        }
    }
}

// ---------------- fused swiglu (tf32-rounded output) ----------------
__global__ void swiglu_fused(const float4* __restrict__ gu, float4* __restrict__ h,
                             int total4, int halfShift, int guStride4) {
    int i = blockIdx.x * blockDim.x + threadIdx.x;
    if (i >= total4) return;
    int row = i >> halfShift;
    int j = i & ((1 << halfShift) - 1);
    long long base = (long long)row * guStride4;
    float4 g = gu[base + j];
    float4 u = gu[base + (1 << halfShift) + j];
    float4 r;
    r.x = tf32r(g.x / (1.f + expf(-g.x)) * u.x);
    r.y = tf32r(g.y / (1.f + expf(-g.y)) * u.y);
    r.z = tf32r(g.z / (1.f + expf(-g.z)) * u.z);
    r.w = tf32r(g.w / (1.f + expf(-g.w)) * u.w);
    h[i] = r;
}

// ---------------- combine ----------------
__global__ void combine_kernel(float* __restrict__ out) {
    int t = blockIdx.x;
    int c = threadIdx.x * 4;
    float4 acc = *(const float4*)(g_shared_out + (size_t)t * CDIM + c);
    #pragma unroll
    for (int k = 0; k < TOPK; k++) {
        float4 v = *(const float4*)(g_rows_out + (size_t)(t * TOPK + k) * CDIM + c);
        acc.x += v.x; acc.y += v.y; acc.z += v.z; acc.w += v.w;
    }
    *(float4*)(out + (size_t)t * CDIM + c) = acc;
}

// ---------------- launch ----------------
extern "C" void kernel_launch(void* const* d_in, const int* in_sizes, int n_in,
                              void* d_out, int out_size) {
    const float* x        = (const float*)d_in[0];
    const float* router_w = (const float*)d_in[1];
    const float* e_bias   = (const float*)d_in[2];
    const float* gate_w   = (const float*)d_in[3];
    const float* up_w     = (const float*)d_in[4];
    const float* down_w   = (const float*)d_in[5];
    const float* sh_gate  = (const float*)d_in[6];
    const float* sh_up    = (const float*)d_in[7];
    const float* sh_down  = (const float*)d_in[8];
    float* out = (float*)d_out;

    float *p_sorted_x, *p_gu_out, *p_hbuf, *p_rows_out, *p_sh_gu, *p_sh_h,
          *p_shared_out, *p_topk_w, *p_x_r;
    float *p_w_gate, *p_w_up, *p_w_down, *p_w_shg, *p_w_shu, *p_w_shd;
    int* p_rowmap;
    cudaGetSymbolAddress((void**)&p_sorted_x,   g_sorted_x);
    cudaGetSymbolAddress((void**)&p_gu_out,     g_gu_out);
    cudaGetSymbolAddress((void**)&p_hbuf,       g_hbuf);
    cudaGetSymbolAddress((void**)&p_rows_out,   g_rows_out);
    cudaGetSymbolAddress((void**)&p_sh_gu,      g_sh_gu);
    cudaGetSymbolAddress((void**)&p_sh_h,       g_sh_h);
    cudaGetSymbolAddress((void**)&p_shared_out, g_shared_out);
    cudaGetSymbolAddress((void**)&p_topk_w,     g_topk_w);
    cudaGetSymbolAddress((void**)&p_rowmap,     g_rowmap);
    cudaGetSymbolAddress((void**)&p_x_r,        g_x_r);
    cudaGetSymbolAddress((void**)&p_w_gate,     g_w_gate);
    cudaGetSymbolAddress((void**)&p_w_up,       g_w_up);
    cudaGetSymbolAddress((void**)&p_w_down,     g_w_down);
    cudaGetSymbolAddress((void**)&p_w_shg,      g_w_shg);
    cudaGetSymbolAddress((void**)&p_w_shu,      g_w_shu);
    cudaGetSymbolAddress((void**)&p_w_shd,      g_w_shd);

    cudaFuncSetAttribute(mma_gemm<false, false>,
                         cudaFuncAttributeMaxDynamicSharedMemorySize, GEMM_SMEM_BYTES);
    cudaFuncSetAttribute(mma_gemm<true, false>,
                         cudaFuncAttributeMaxDynamicSharedMemorySize, GEMM_SMEM_BYTES);
    cudaFuncSetAttribute(mma_gemm<true, true>,
                         cudaFuncAttributeMaxDynamicSharedMemorySize, GEMM_SMEM_BYTES);

    long long n4;

    // ---- prep needed by the shared expert (launches 0-2) ----
    n4 = (long long)S_TOK * CDIM / 4;
    round_copy<<<(unsigned)((n4 + 255) / 256), 256>>>((const float4*)x, (float4*)p_x_r, n4);
    n4 = (long long)CDIM * HSHARED / 4;
    round_copy<<<(unsigned)((n4 + 255) / 256), 256>>>((const float4*)sh_gate, (float4*)p_w_shg, n4);
    round_copy<<<(unsigned)((n4 + 255) / 256), 256>>>((const float4*)sh_up,   (float4*)p_w_shu, n4);

    // ---- routing part 1 (launches 3-4) ----
    zero_counts_kernel<<<1, 64>>>();
    router_kernel<<<S_TOK, 256>>>(x, router_w, e_bias);

    // ---- launch #5: shared-expert gu GEMM (profiled by ncu -s 5 -c 1) ----
    mma_gemm<false, false><<<dim3(4096 / 256, S_TOK / 128), GEMM_THREADS, GEMM_SMEM_BYTES>>>(
        p_x_r, p_w_shg, p_w_shu, p_sh_gu, 1024, 2048, 4096, 0, nullptr, nullptr);
    {
        int total4 = S_TOK * (HSHARED / 4);
        swiglu_fused<<<(total4 + 255) / 256, 256>>>(
            (const float4*)p_sh_gu, (float4*)p_sh_h, total4, 9, 1024);
    }
    n4 = (long long)CDIM * HSHARED / 4;
    round_copy<<<(unsigned)((n4 + 255) / 256), 256>>>((const float4*)sh_down, (float4*)p_w_shd, n4);
    mma_gemm<false, false><<<dim3(1024 / 256, S_TOK / 128), GEMM_THREADS, GEMM_SMEM_BYTES>>>(
        p_sh_h, p_w_shd, nullptr, p_shared_out, 2048, 1024, 1024, 0, nullptr, nullptr);

    // ---- prep expert weights + routing part 2 ----
    n4 = (long long)EXP * CDIM * HDIM / 4;
    round_copy<<<(unsigned)((n4 + 255) / 256), 256>>>((const float4*)gate_w, (float4*)p_w_gate, n4);
    round_copy<<<(unsigned)((n4 + 255) / 256), 256>>>((const float4*)up_w,   (float4*)p_w_up,   n4);
    round_copy<<<(unsigned)((n4 + 255) / 256), 256>>>((const float4*)down_w, (float4*)p_w_down, n4);
    setup_kernel<<<1, 1>>>();
    assign_kernel<<<NROWS / 256, 256>>>();
    gather_kernel<<<NROWS, 256>>>(x);

    // ---- routed experts: gu = sorted_x @ [gate | up]  (K=1024, Nb=512, N=1024) ----
    mma_gemm<true, false><<<dim3(1024 / 256, MAX_TILES), GEMM_THREADS, GEMM_SMEM_BYTES>>>(
        p_sorted_x, p_w_gate, p_w_up, p_gu_out, 1024, 512, 1024,
        (long long)CDIM * HDIM, nullptr, nullptr);
    {
        int total4 = NROWS * (HDIM / 4);
        swiglu_fused<<<(total4 + 255) / 256, 256>>>(
            (const float4*)p_gu_out, (float4*)p_hbuf, total4, 7, 256);
    }
    mma_gemm<true, true><<<dim3(1024 / 256, MAX_TILES), GEMM_THREADS, GEMM_SMEM_BYTES>>>(
        p_hbuf, p_w_down, nullptr, p_rows_out, 512, 1024, 1024,
        (long long)HDIM * CDIM, p_rowmap, p_topk_w);

    // ---- combine ----
    combine_kernel<<<S_TOK, 256>>>(out);
}

// round 6
// speedup vs baseline: 1.4481x; 1.4481x over previous
#include <cuda_runtime.h>
#include <cuda_fp16.h>
#include <math.h>
#include <stdint.h>

// ---------------- problem constants ----------------
#define S_TOK   4096
#define CDIM    1024
#define EXP     64
#define TOPK    8
#define NGRP    8
#define EPG     8
#define TGRP    4
#define HDIM    512
#define HSHARED 2048
#define NROWS   (S_TOK * TOPK)   // 32768
#define MAX_TILES 320

// ---------------- scratch (static device globals) ----------------
struct TileDesc { int e; int row_start; int rows; };

__device__ int      g_counts[EXP];
__device__ int      g_offsets[EXP + 1];
__device__ int      g_cursor[EXP];
__device__ TileDesc g_tiles[MAX_TILES];
__device__ int      g_ntiles;
__device__ int      g_rowmap[NROWS];
__device__ int      g_topk_idx[NROWS];
__device__ float    g_topk_w[NROWS];

__device__ __half   g_sorted_x[(size_t)NROWS * CDIM];
__device__ float    g_gu_out[(size_t)NROWS * 1024];
__device__ __half   g_hbuf[(size_t)NROWS * HDIM];
__device__ float    g_rows_out[(size_t)NROWS * CDIM];
__device__ float    g_sh_gu[(size_t)S_TOK * 4096];
__device__ __half   g_sh_h[(size_t)S_TOK * HSHARED];
__device__ float    g_shared_out[(size_t)S_TOK * CDIM];
__device__ __half   g_x_r[(size_t)S_TOK * CDIM];

// fp16 weight copies (native [K][N] layouts preserved)
__device__ __half   g_w_gate[(size_t)EXP * CDIM * HDIM];
__device__ __half   g_w_up[(size_t)EXP * CDIM * HDIM];
__device__ __half   g_w_down[(size_t)EXP * HDIM * CDIM];
__device__ __half   g_w_shg[(size_t)CDIM * HSHARED];
__device__ __half   g_w_shu[(size_t)CDIM * HSHARED];
__device__ __half   g_w_shd[(size_t)HSHARED * CDIM];

// ---------------- helpers ----------------
__device__ __forceinline__ void mma_f16(float* c, const uint32_t* a, const uint32_t* b) {
    asm volatile(
        "mma.sync.aligned.m16n8k16.row.col.f32.f16.f16.f32 "
        "{%0,%1,%2,%3}, {%4,%5,%6,%7}, {%8,%9}, {%0,%1,%2,%3};"
        : "+f"(c[0]), "+f"(c[1]), "+f"(c[2]), "+f"(c[3])
        : "r"(a[0]), "r"(a[1]), "r"(a[2]), "r"(a[3]), "r"(b[0]), "r"(b[1]));
}
__device__ __forceinline__ void ldmatrix_x4(uint32_t* r, uint32_t addr) {
    asm volatile("ldmatrix.sync.aligned.m8n8.x4.shared.b16 {%0,%1,%2,%3}, [%4];"
                 : "=r"(r[0]), "=r"(r[1]), "=r"(r[2]), "=r"(r[3]) : "r"(addr));
}
__device__ __forceinline__ void ldmatrix_x4_trans(uint32_t* r, uint32_t addr) {
    asm volatile("ldmatrix.sync.aligned.m8n8.x4.trans.shared.b16 {%0,%1,%2,%3}, [%4];"
                 : "=r"(r[0]), "=r"(r[1]), "=r"(r[2]), "=r"(r[3]) : "r"(addr));
}
__device__ __forceinline__ void cp_async16(uint32_t dst, const void* src, int srcbytes) {
    asm volatile("cp.async.cg.shared.global [%0], [%1], 16, %2;"
                 :: "r"(dst), "l"(src), "r"(srcbytes));
}

// ---------------- prep: f32 -> f16 convert copy ----------------
__global__ void half_copy(const float4* __restrict__ src, __half2* __restrict__ dst,
                          long long n4) {
    long long i = (long long)blockIdx.x * blockDim.x + threadIdx.x;
    if (i >= n4) return;
    float4 v = src[i];
    dst[i * 2 + 0] = __floats2half2_rn(v.x, v.y);
    dst[i * 2 + 1] = __floats2half2_rn(v.z, v.w);
}

// ---------------- routing kernels (verified correct) ----------------
__global__ void zero_counts_kernel() {
    if (threadIdx.x < EXP) g_counts[threadIdx.x] = 0;
}

__global__ void router_kernel(const float* __restrict__ x,
                              const float* __restrict__ rw,
                              const float* __restrict__ ebias) {
    int t = blockIdx.x;
    __shared__ float xs[CDIM];
    __shared__ float sc[EXP];

    const float* xrow = x + (size_t)t * CDIM;
    for (int c = threadIdx.x * 4; c < CDIM; c += blockDim.x * 4)
        *(float4*)&xs[c] = *(const float4*)&xrow[c];
    __syncthreads();

    int wid = threadIdx.x >> 5, lane = threadIdx.x & 31;
    for (int i = 0; i < 8; i++) {
        int e = wid * 8 + i;
        const float* w = rw + (size_t)e * CDIM;
        float s = 0.f;
        for (int c = lane; c < CDIM; c += 32) s += xs[c] * w[c];
        #pragma unroll
        for (int o = 16; o > 0; o >>= 1) s += __shfl_xor_sync(0xffffffffu, s, o);
        if (lane == 0) sc[e] = 1.f / (1.f + expf(-s));
    }
    __syncthreads();

    if (threadIdx.x == 0) {
        float sb[EXP];
        for (int e = 0; e < EXP; e++) sb[e] = sc[e] + ebias[e];
        float grp[NGRP];
        for (int g = 0; g < NGRP; g++) {
            float m1 = -1e30f, m2 = -1e30f;
            for (int j = 0; j < EPG; j++) {
                float v = sb[g * EPG + j];
                if (v > m1) { m2 = m1; m1 = v; }
                else if (v > m2) m2 = v;
            }
            grp[g] = m1 + m2;
        }
        bool gsel[NGRP] = {};
        for (int it = 0; it < TGRP; it++) {
            float best = -1e30f; int bi = 0;
            for (int g = 0; g < NGRP; g++)
                if (!gsel[g] && grp[g] > best) { best = grp[g]; bi = g; }
            gsel[bi] = true;
        }
        bool eused[EXP] = {};
        int idx[TOPK]; float wv[TOPK]; float wsum = 0.f;
        for (int it = 0; it < TOPK; it++) {
            float best = -1e30f; int bi = 0;
            for (int e = 0; e < EXP; e++)
                if (gsel[e / EPG] && !eused[e] && sb[e] > best) { best = sb[e]; bi = e; }
            eused[bi] = true; idx[it] = bi;
            wv[it] = sc[bi]; wsum += sc[bi];
        }
        float inv = 1.f / (wsum + 1e-20f);
        for (int it = 0; it < TOPK; it++) {
            g_topk_idx[t * TOPK + it] = idx[it];
            g_topk_w[t * TOPK + it]   = wv[it] * inv;
            atomicAdd(&g_counts[idx[it]], 1);
        }
    }
}

__global__ void setup_kernel() {
    int off = 0, nt = 0;
    for (int e = 0; e < EXP; e++) {
        g_offsets[e] = off;
        g_cursor[e]  = off;
        int c = g_counts[e];
        for (int r = 0; r < c; r += 128) {
            g_tiles[nt].e = e;
            g_tiles[nt].row_start = off + r;
            g_tiles[nt].rows = min(128, c - r);
            nt++;
        }
        off += c;
    }
    g_offsets[EXP] = off;
    g_ntiles = nt;
}

__global__ void assign_kernel() {
    int d = blockIdx.x * blockDim.x + threadIdx.x;
    if (d >= NROWS) return;
    int e = g_topk_idx[d];
    int pos = atomicAdd(&g_cursor[e], 1);
    g_rowmap[pos] = d;
}

// gather + fp16 convert into sorted order
__global__ void gather_kernel(const float* __restrict__ x) {
    int row = blockIdx.x;
    int d = g_rowmap[row];
    int t = d / TOPK;
    const float4* src = (const float4*)(x + (size_t)t * CDIM);
    __half2* dst = (__half2*)(g_sorted_x + (size_t)row * CDIM);
    for (int i = threadIdx.x; i < CDIM / 4; i += blockDim.x) {
        float4 v = src[i];
        dst[i * 2 + 0] = __floats2half2_rn(v.x, v.y);
        dst[i * 2 + 1] = __floats2half2_rn(v.z, v.w);
    }
}

// ================= fp16 tensor-core GEMM (cp.async 4-stage, ldmatrix) =================
// C[M,N] = A[M,Kd] @ B[Kd,N]; fp16 operands, fp32 accum/output.
// B row-major [k][n] (native). BM=128, BN=256, BK=32. 8 warps (2x4), warp tile 64x64.
#define GEMM_THREADS 256
#define STAGES 4
#define A_STRIDE_H 40                       // halfs per A row (80 B; conflict-free phases)
#define B_STRIDE_H 264                      // halfs per B row (528 B; conflict-free phases)
#define A_SZ_H (128 * A_STRIDE_H)           // 5120 halfs = 10240 B
#define B_SZ_H (32 * B_STRIDE_H)            // 8448 halfs = 16896 B
#define GEMM_SMEM_BYTES (STAGES * (A_SZ_H + B_SZ_H) * 2)   // 108,544 B

template <bool GROUPED, bool SCATTER>
__global__ void __launch_bounds__(GEMM_THREADS, 1) mma_gemm(
    const __half* __restrict__ A, const __half* __restrict__ B0,
    const __half* __restrict__ B1, float* __restrict__ Cout,
    int Kd, int Nb, int N, long long strideB,
    const int* __restrict__ rowmap, const float* __restrict__ rowscale) {
    extern __shared__ __half smem_h[];

    int row_start, rows, e;
    if (GROUPED) {
        if ((int)blockIdx.y >= g_ntiles) return;
        TileDesc td = g_tiles[blockIdx.y];
        e = td.e; row_start = td.row_start; rows = td.rows;
    } else {
        e = 0; row_start = blockIdx.y * 128; rows = 128;
    }
    int nstart = blockIdx.x * 256;
    const __half* Bm = (nstart < Nb) ? B0 : B1;
    int ncol0 = (nstart < Nb) ? nstart : nstart - Nb;
    const __half* Bptr = Bm + (long long)e * strideB + ncol0;
    const __half* Aptr = A + (long long)row_start * Kd;

    int tid = threadIdx.x;
    int lane = tid & 31, wid = tid >> 5;
    int g = lane >> 2, tig = lane & 3;
    int wmb = (wid >> 2) * 64;
    int wnb = (wid & 3) * 64;

    uint32_t sb = (uint32_t)__cvta_generic_to_shared(smem_h);

    float acc[4][8][4];
    #pragma unroll
    for (int mi = 0; mi < 4; mi++)
        #pragma unroll
        for (int ni = 0; ni < 8; ni++)
            #pragma unroll
            for (int q = 0; q < 4; q++) acc[mi][ni][q] = 0.f;

    const int T = Kd >> 5;

    // issue one K-tile (BK=32) into `stage`
    auto issue = [&](int stage, int it) {
        int kk = it * 32;
        uint32_t abase = sb + (uint32_t)(stage * A_SZ_H) * 2u;
        uint32_t bbase = sb + (uint32_t)(STAGES * A_SZ_H + stage * B_SZ_H) * 2u;
        // A tile: 128 rows x 4 chunks(8 halfs)  = 512 chunks, 2/thread
        #pragma unroll
        for (int i = 0; i < 2; i++) {
            int c = tid + i * 256;
            int r = c >> 2, j = c & 3;
            const __half* src = Aptr + (long long)r * Kd + kk + j * 8;
            int vb = 16;
            if (GROUPED && r >= rows) { vb = 0; src = Aptr; }
            cp_async16(abase + (uint32_t)(r * A_STRIDE_H + j * 8) * 2u, src, vb);
        }
        // B tile: 32 rows x 32 chunks = 1024 chunks, 4/thread
        #pragma unroll
        for (int i = 0; i < 4; i++) {
            int c = tid + i * 256;
            int r = c >> 5, j = c & 31;
            cp_async16(bbase + (uint32_t)(r * B_STRIDE_H + j * 8) * 2u,
                       Bptr + (long long)(kk + r) * Nb + j * 8, 16);
        }
        asm volatile("cp.async.commit_group;" ::: "memory");
    };

    issue(0, 0);
    issue(1, 1);
    issue(2, 2);

    // ldmatrix lane addressing (bytes, within a stage)
    int lhalf = lane & 15, lsel8 = (lane >> 4) << 3;
    for (int it = 0; it < T; it++) {
        int stage = it & 3;
        asm volatile("cp.async.wait_group 2;" ::: "memory");
        __syncthreads();
        if (it + 3 < T) issue((it + 3) & 3, it + 3);

        uint32_t abase = sb + (uint32_t)(stage * A_SZ_H) * 2u;
        uint32_t bbase = sb + (uint32_t)(STAGES * A_SZ_H + stage * B_SZ_H) * 2u;

        #pragma unroll
        for (int ks = 0; ks < 2; ks++) {
            int k0 = ks * 16;
            uint32_t af[4][4], bf[4][4];
            #pragma unroll
            for (int mi = 0; mi < 4; mi++) {
                int arow = wmb + mi * 16 + lhalf;
                int acol = k0 + lsel8;
                ldmatrix_x4(af[mi], abase + (uint32_t)(arow * A_STRIDE_H + acol) * 2u);
            }
            #pragma unroll
            for (int nc = 0; nc < 4; nc++) {
                int krow = k0 + lhalf;
                int bcol = wnb + nc * 16 + lsel8;
                ldmatrix_x4_trans(bf[nc], bbase + (uint32_t)(krow * B_STRIDE_H + bcol) * 2u);
            }
            #pragma unroll
            for (int mi = 0; mi < 4; mi++)
                #pragma unroll
                for (int nc = 0; nc < 4; nc++) {
                    mma_f16(acc[mi][2 * nc + 0], af[mi], &bf[nc][0]);
                    mma_f16(acc[mi][2 * nc + 1], af[mi], &bf[nc][2]);
                }
        }
    }

    // ---- epilogue (c layout identical to tf32 path) ----
    #pragma unroll
    for (int mi = 0; mi < 4; mi++) {
        #pragma unroll
        for (int h = 0; h < 2; h++) {
            int rl = wmb + mi * 16 + g + 8 * h;
            if (GROUPED && rl >= rows) continue;
            float scale = 1.f;
            float* dst;
            if (SCATTER) {
                int d = rowmap[row_start + rl];
                scale = rowscale[d];
                dst = Cout + (size_t)d * N;
            } else {
                dst = Cout + (size_t)(row_start + rl) * N;
            }
            #pragma unroll
            for (int ni = 0; ni < 8; ni++) {
                int col = nstart + wnb + ni * 8 + 2 * tig;
                float2 v;
                v.x = acc[mi][ni][2 * h + 0] * scale;
                v.y = acc[mi][ni][2 * h + 1] * scale;
                *(float2*)(dst + col) = v;
            }
        }
    }
}

// ---------------- fused swiglu: h = silu(gu[:, :half]) * gu[:, half:]  (fp16 out) ----------------
__global__ void swiglu_fused(const float4* __restrict__ gu, __half2* __restrict__ h,
                             int total4, int halfShift, int guStride4) {
    int i = blockIdx.x * blockDim.x + threadIdx.x;
    if (i >= total4) return;
    int row = i >> halfShift;
    int j = i & ((1 << halfShift) - 1);
    long long base = (long long)row * guStride4;
    float4 g = gu[base + j];
    float4 u = gu[base + (1 << halfShift) + j];
    float rx = g.x / (1.f + expf(-g.x)) * u.x;
    float ry = g.y / (1.f + expf(-g.y)) * u.y;
    float rz = g.z / (1.f + expf(-g.z)) * u.z;
    float rw = g.w / (1.f + expf(-g.w)) * u.w;
    h[i * 2 + 0] = __floats2half2_rn(rx, ry);
    h[i * 2 + 1] = __floats2half2_rn(rz, rw);
}

// ---------------- combine ----------------
__global__ void combine_kernel(float* __restrict__ out) {
    int t = blockIdx.x;
    int c = threadIdx.x * 4;
    float4 acc = *(const float4*)(g_shared_out + (size_t)t * CDIM + c);
    #pragma unroll
    for (int k = 0; k < TOPK; k++) {
        float4 v = *(const float4*)(g_rows_out + (size_t)(t * TOPK + k) * CDIM + c);
        acc.x += v.x; acc.y += v.y; acc.z += v.z; acc.w += v.w;
    }
    *(float4*)(out + (size_t)t * CDIM + c) = acc;
}

// ---------------- launch ----------------
extern "C" void kernel_launch(void* const* d_in, const int* in_sizes, int n_in,
                              void* d_out, int out_size) {
    const float* x        = (const float*)d_in[0];
    const float* router_w = (const float*)d_in[1];
    const float* e_bias   = (const float*)d_in[2];
    const float* gate_w   = (const float*)d_in[3];
    const float* up_w     = (const float*)d_in[4];
    const float* down_w   = (const float*)d_in[5];
    const float* sh_gate  = (const float*)d_in[6];
    const float* sh_up    = (const float*)d_in[7];
    const float* sh_down  = (const float*)d_in[8];
    float* out = (float*)d_out;

    __half *p_sorted_x, *p_hbuf, *p_sh_h, *p_x_r;
    __half *p_w_gate, *p_w_up, *p_w_down, *p_w_shg, *p_w_shu, *p_w_shd;
    float *p_gu_out, *p_rows_out, *p_sh_gu, *p_shared_out, *p_topk_w;
    int* p_rowmap;
    cudaGetSymbolAddress((void**)&p_sorted_x,   g_sorted_x);
    cudaGetSymbolAddress((void**)&p_gu_out,     g_gu_out);
    cudaGetSymbolAddress((void**)&p_hbuf,       g_hbuf);
    cudaGetSymbolAddress((void**)&p_rows_out,   g_rows_out);
    cudaGetSymbolAddress((void**)&p_sh_gu,      g_sh_gu);
    cudaGetSymbolAddress((void**)&p_sh_h,       g_sh_h);
    cudaGetSymbolAddress((void**)&p_shared_out, g_shared_out);
    cudaGetSymbolAddress((void**)&p_topk_w,     g_topk_w);
    cudaGetSymbolAddress((void**)&p_rowmap,     g_rowmap);
    cudaGetSymbolAddress((void**)&p_x_r,        g_x_r);
    cudaGetSymbolAddress((void**)&p_w_gate,     g_w_gate);
    cudaGetSymbolAddress((void**)&p_w_up,       g_w_up);
    cudaGetSymbolAddress((void**)&p_w_down,     g_w_down);
    cudaGetSymbolAddress((void**)&p_w_shg,      g_w_shg);
    cudaGetSymbolAddress((void**)&p_w_shu,      g_w_shu);
    cudaGetSymbolAddress((void**)&p_w_shd,      g_w_shd);

    cudaFuncSetAttribute(mma_gemm<false, false>,
                         cudaFuncAttributeMaxDynamicSharedMemorySize, GEMM_SMEM_BYTES);
    cudaFuncSetAttribute(mma_gemm<true, false>,
                         cudaFuncAttributeMaxDynamicSharedMemorySize, GEMM_SMEM_BYTES);
    cudaFuncSetAttribute(mma_gemm<true, true>,
                         cudaFuncAttributeMaxDynamicSharedMemorySize, GEMM_SMEM_BYTES);

    long long n4;

    // ---- prep needed by the shared expert (launches 0-2) ----
    n4 = (long long)S_TOK * CDIM / 4;
    half_copy<<<(unsigned)((n4 + 255) / 256), 256>>>((const float4*)x, (__half2*)p_x_r, n4);
    n4 = (long long)CDIM * HSHARED / 4;
    half_copy<<<(unsigned)((n4 + 255) / 256), 256>>>((const float4*)sh_gate, (__half2*)p_w_shg, n4);
    half_copy<<<(unsigned)((n4 + 255) / 256), 256>>>((const float4*)sh_up,   (__half2*)p_w_shu, n4);

    // ---- routing part 1 (launches 3-4) ----
    zero_counts_kernel<<<1, 64>>>();
    router_kernel<<<S_TOK, 256>>>(x, router_w, e_bias);

    // ---- launch #5: shared-expert gu GEMM (profiled by ncu -s 5 -c 1) ----
    mma_gemm<false, false><<<dim3(4096 / 256, S_TOK / 128), GEMM_THREADS, GEMM_SMEM_BYTES>>>(
        p_x_r, p_w_shg, p_w_shu, p_sh_gu, 1024, 2048, 4096, 0, nullptr, nullptr);
    {
        int total4 = S_TOK * (HSHARED / 4);
        swiglu_fused<<<(total4 + 255) / 256, 256>>>(
            (const float4*)p_sh_gu, (__half2*)p_sh_h, total4, 9, 1024);
    }
    n4 = (long long)CDIM * HSHARED / 4;
    half_copy<<<(unsigned)((n4 + 255) / 256), 256>>>((const float4*)sh_down, (__half2*)p_w_shd, n4);
    mma_gemm<false, false><<<dim3(1024 / 256, S_TOK / 128), GEMM_THREADS, GEMM_SMEM_BYTES>>>(
        p_sh_h, p_w_shd, nullptr, p_shared_out, 2048, 1024, 1024, 0, nullptr, nullptr);

    // ---- prep expert weights + routing part 2 ----
    n4 = (long long)EXP * CDIM * HDIM / 4;
    half_copy<<<(unsigned)((n4 + 255) / 256), 256>>>((const float4*)gate_w, (__half2*)p_w_gate, n4);
    half_copy<<<(unsigned)((n4 + 255) / 256), 256>>>((const float4*)up_w,   (__half2*)p_w_up,   n4);
    half_copy<<<(unsigned)((n4 + 255) / 256), 256>>>((const float4*)down_w, (__half2*)p_w_down, n4);
    setup_kernel<<<1, 1>>>();
    assign_kernel<<<NROWS / 256, 256>>>();
    gather_kernel<<<NROWS, 256>>>(x);

    // ---- routed experts: gu = sorted_x @ [gate | up]  (K=1024, Nb=512, N=1024) ----
    mma_gemm<true, false><<<dim3(1024 / 256, MAX_TILES), GEMM_THREADS, GEMM_SMEM_BYTES>>>(
        p_sorted_x, p_w_gate, p_w_up, p_gu_out, 1024, 512, 1024,
        (long long)CDIM * HDIM, nullptr, nullptr);
    {
        int total4 = NROWS * (HDIM / 4);
        swiglu_fused<<<(total4 + 255) / 256, 256>>>(
            (const float4*)p_gu_out, (__half2*)p_hbuf, total4, 7, 256);
    }
    mma_gemm<true, true><<<dim3(1024 / 256, MAX_TILES), GEMM_THREADS, GEMM_SMEM_BYTES>>>(
        p_hbuf, p_w_down, nullptr, p_rows_out, 512, 1024, 1024,
        (long long)HDIM * CDIM, p_rowmap, p_topk_w);

    // ---- combine ----
    combine_kernel<<<S_TOK, 256>>>(out);
}